// round 1
// baseline (speedup 1.0000x reference)
#include <cuda_runtime.h>
#include <math.h>

#define BATCH   65536
#define KDIM    512
#define OUTA    256     // actor width
#define HID     64
#define N_W     576     // 256 + 256 + 64
#define N_A     1024    // 512 + 512

#define BM 128
#define BN 64
#define BK 16
#define TM 8
#define TN 4
// threads = (BM/TM) * (BN/TN) = 16 * 16 = 256

// ---------------- scratch (static device globals; no runtime alloc) -------
__device__ float g_y12[(size_t)BATCH * 512];     // y1 cols [0,256), y2 cols [256,512)
__device__ float g_h[(size_t)BATCH * HID];       // chooser pre-activation
__device__ float g_qpart[16][BATCH];             // per-ntile quadratic partials

// =========================================================================
// GEMM-W: C = x @ [W1; W2; Wc1]^T   (all three stored row-major [N_rows, 512])
// =========================================================================
__global__ __launch_bounds__(256) void gemm_w_kernel(
    const float* __restrict__ x,
    const float* __restrict__ W1,
    const float* __restrict__ W2,
    const float* __restrict__ Wc1)
{
    __shared__ float As[BK][BM];     // transposed x tile: As[k][m]
    __shared__ float Bs[BK][BN];     // Bs[k][n]

    const int nblk = blockIdx.x;     // 0..8
    const int mblk = blockIdx.y;     // 0..511
    const int tid  = threadIdx.x;
    const int tn   = tid & 15;       // 0..15
    const int tm   = tid >> 4;       // 0..15
    const int row0 = mblk * BM;
    const int col0 = nblk * BN;

    float acc[TM][TN];
#pragma unroll
    for (int i = 0; i < TM; i++)
#pragma unroll
        for (int j = 0; j < TN; j++) acc[i][j] = 0.f;

    // Per-thread B-tile load coords: one float4 along k
    const int bn   = tid >> 2;       // 0..63  (column within tile)
    const int bk4  = tid & 3;        // 0..3   (float4 slot within k-chunk)
    // resolve weight row pointer once (col region is tile-invariant: 576 = 4.5*... all
    // region boundaries are multiples of 64 so a 64-wide tile never straddles)
    const int jcol = col0 + bn;
    const float* wrow;
    if (jcol < 256)       wrow = W1  + (size_t)jcol * KDIM;
    else if (jcol < 512)  wrow = W2  + (size_t)(jcol - 256) * KDIM;
    else                  wrow = Wc1 + (size_t)(jcol - 512) * KDIM;

    for (int k0 = 0; k0 < KDIM; k0 += BK) {
        // load x tile: 128x16 floats = 512 float4, 2 per thread
#pragma unroll
        for (int it = 0; it < 2; it++) {
            int lin = tid + it * 256;          // 0..511
            int row = lin >> 2;                // 0..127
            int c4  = lin & 3;                 // 0..3
            float4 v = *(const float4*)(x + (size_t)(row0 + row) * KDIM + k0 + c4 * 4);
            As[c4 * 4 + 0][row] = v.x;
            As[c4 * 4 + 1][row] = v.y;
            As[c4 * 4 + 2][row] = v.z;
            As[c4 * 4 + 3][row] = v.w;
        }
        // load W tile (transpose into Bs[k][n])
        {
            float4 v = *(const float4*)(wrow + k0 + bk4 * 4);
            Bs[bk4 * 4 + 0][bn] = v.x;
            Bs[bk4 * 4 + 1][bn] = v.y;
            Bs[bk4 * 4 + 2][bn] = v.z;
            Bs[bk4 * 4 + 3][bn] = v.w;
        }
        __syncthreads();

#pragma unroll
        for (int kk = 0; kk < BK; kk++) {
            float a[TM], b[TN];
            float4 a0 = *(const float4*)&As[kk][tm * TM];
            float4 a1 = *(const float4*)&As[kk][tm * TM + 4];
            a[0]=a0.x; a[1]=a0.y; a[2]=a0.z; a[3]=a0.w;
            a[4]=a1.x; a[5]=a1.y; a[6]=a1.z; a[7]=a1.w;
            float4 bb = *(const float4*)&Bs[kk][tn * TN];
            b[0]=bb.x; b[1]=bb.y; b[2]=bb.z; b[3]=bb.w;
#pragma unroll
            for (int i = 0; i < TM; i++)
#pragma unroll
                for (int j = 0; j < TN; j++)
                    acc[i][j] = fmaf(a[i], b[j], acc[i][j]);
        }
        __syncthreads();
    }

    // store: cols <512 -> g_y12, cols >=512 -> g_h
    const int cbase = col0 + tn * TN;
#pragma unroll
    for (int i = 0; i < TM; i++) {
        int row = row0 + tm * TM + i;
        float4 v = make_float4(acc[i][0], acc[i][1], acc[i][2], acc[i][3]);
        if (cbase < 512)
            *(float4*)(g_y12 + (size_t)row * 512 + cbase) = v;
        else
            *(float4*)(g_h + (size_t)row * HID + (cbase - 512)) = v;
    }
}

// =========================================================================
// GEMM-A: T = x @ [A1 | A2]  (A row-major [512,512], i.e. B[k][n]=A[k*512+n]),
// fused row-dot with x -> per-tile quadratic partials in g_qpart[nblk][row].
// =========================================================================
__global__ __launch_bounds__(256) void gemm_a_kernel(
    const float* __restrict__ x,
    const float* __restrict__ A1,
    const float* __restrict__ A2)
{
    __shared__ float As[BK][BM];
    __shared__ float Bs[BK][BN];
    __shared__ float red[BM][16];

    const int nblk = blockIdx.x;     // 0..15
    const int mblk = blockIdx.y;     // 0..511
    const int tid  = threadIdx.x;
    const int tn   = tid & 15;
    const int tm   = tid >> 4;
    const int row0 = mblk * BM;
    const int col0 = nblk * BN;

    const float* Amat = (col0 < 512) ? A1 : A2;
    const int    cmod0 = (col0 < 512) ? col0 : (col0 - 512);

    float acc[TM][TN];
#pragma unroll
    for (int i = 0; i < TM; i++)
#pragma unroll
        for (int j = 0; j < TN; j++) acc[i][j] = 0.f;

    // B-tile load coords: Bs is [K,N]-contiguous in N -> direct float4 copy
    const int bkr = tid >> 4;        // k row 0..15
    const int bn4 = tid & 15;        // float4 col slot 0..15

    for (int k0 = 0; k0 < KDIM; k0 += BK) {
#pragma unroll
        for (int it = 0; it < 2; it++) {
            int lin = tid + it * 256;
            int row = lin >> 2;
            int c4  = lin & 3;
            float4 v = *(const float4*)(x + (size_t)(row0 + row) * KDIM + k0 + c4 * 4);
            As[c4 * 4 + 0][row] = v.x;
            As[c4 * 4 + 1][row] = v.y;
            As[c4 * 4 + 2][row] = v.z;
            As[c4 * 4 + 3][row] = v.w;
        }
        {
            float4 v = *(const float4*)(Amat + (size_t)(k0 + bkr) * 512 + cmod0 + bn4 * 4);
            *(float4*)&Bs[bkr][bn4 * 4] = v;
        }
        __syncthreads();

#pragma unroll
        for (int kk = 0; kk < BK; kk++) {
            float a[TM], b[TN];
            float4 a0 = *(const float4*)&As[kk][tm * TM];
            float4 a1 = *(const float4*)&As[kk][tm * TM + 4];
            a[0]=a0.x; a[1]=a0.y; a[2]=a0.z; a[3]=a0.w;
            a[4]=a1.x; a[5]=a1.y; a[6]=a1.z; a[7]=a1.w;
            float4 bb = *(const float4*)&Bs[kk][tn * TN];
            b[0]=bb.x; b[1]=bb.y; b[2]=bb.z; b[3]=bb.w;
#pragma unroll
            for (int i = 0; i < TM; i++)
#pragma unroll
                for (int j = 0; j < TN; j++)
                    acc[i][j] = fmaf(a[i], b[j], acc[i][j]);
        }
        __syncthreads();
    }

    // fused quadratic partial: sum_j T[i][j] * x[i][cmod0 + j]
    const int ccol = cmod0 + tn * TN;
#pragma unroll
    for (int i = 0; i < TM; i++) {
        int row = row0 + tm * TM + i;
        float4 xv = *(const float4*)(x + (size_t)row * KDIM + ccol);
        float p = acc[i][0] * xv.x + acc[i][1] * xv.y + acc[i][2] * xv.z + acc[i][3] * xv.w;
        red[tm * TM + i][tn] = p;
    }
    __syncthreads();

    if (tid < BM) {
        float s = 0.f;
#pragma unroll
        for (int t = 0; t < 16; t++) s += red[tid][t];
        g_qpart[nblk][row0 + tid] = s;
    }
}

// =========================================================================
// Epilogue: chooser MLP + gated mixes.  One warp per batch row.
// =========================================================================
__global__ __launch_bounds__(256) void epilogue_kernel(
    const float* __restrict__ x,
    const float* __restrict__ b1, const float* __restrict__ c1,
    const float* __restrict__ b2, const float* __restrict__ c2,
    const float* __restrict__ bc1,
    const float* __restrict__ Wc2, const float* __restrict__ bc2,
    float* __restrict__ out)
{
    const int warp = threadIdx.x >> 5;
    const int lane = threadIdx.x & 31;
    const int r = blockIdx.x * 8 + warp;

    // ---- chooser: h = relu(z + bc1); logits = h @ Wc2^T + bc2 ----
    float p0 = 0.f, p1 = 0.f;
#pragma unroll
    for (int t = 0; t < 2; t++) {
        int j = lane * 2 + t;                       // 0..63
        float h = g_h[(size_t)r * HID + j] + bc1[j];
        h = fmaxf(h, 0.f);
        p0 = fmaf(h, Wc2[j],       p0);
        p1 = fmaf(h, Wc2[64 + j],  p1);
    }
#pragma unroll
    for (int o = 16; o; o >>= 1) {
        p0 += __shfl_xor_sync(0xffffffffu, p0, o);
        p1 += __shfl_xor_sync(0xffffffffu, p1, o);
    }
    float s0 = 1.f / (1.f + expf(-(p0 + bc2[0])));
    float s1 = 1.f / (1.f + expf(-(p1 + bc2[1])));

    // ---- x·b1, x·b2 ----
    float xb1 = 0.f, xb2 = 0.f;
    const float4* xr  = (const float4*)(x + (size_t)r * KDIM);
    const float4* pb1 = (const float4*)b1;
    const float4* pb2 = (const float4*)b2;
#pragma unroll
    for (int t = 0; t < 4; t++) {
        int idx = lane + t * 32;
        float4 v  = xr[idx];
        float4 w1 = pb1[idx];
        float4 w2 = pb2[idx];
        xb1 += v.x * w1.x + v.y * w1.y + v.z * w1.z + v.w * w1.w;
        xb2 += v.x * w2.x + v.y * w2.y + v.z * w2.z + v.w * w2.w;
    }
#pragma unroll
    for (int o = 16; o; o >>= 1) {
        xb1 += __shfl_xor_sync(0xffffffffu, xb1, o);
        xb2 += __shfl_xor_sync(0xffffffffu, xb2, o);
    }

    // ---- quadratic partial sums (deterministic, no atomics) ----
    float v = (lane < 16) ? g_qpart[lane][r] : 0.f;
    float qa = (lane < 8)  ? v : 0.f;                 // A1 tiles 0..7
    float qb = (lane >= 8) ? v : 0.f;                 // A2 tiles 8..15
#pragma unroll
    for (int o = 16; o; o >>= 1) {
        qa += __shfl_xor_sync(0xffffffffu, qa, o);
        qb += __shfl_xor_sync(0xffffffffu, qb, o);
    }

    if (lane == 0) {
        float q1 = qa + xb1 + c1[0];
        float q2 = qb + xb2 + c2[0];
        out[(size_t)BATCH * OUTA + r] = s0 * q1 + s1 * q2;
    }

    // ---- actor: sigma-gated mix of y1, y2 ----
    const float4* y1 = (const float4*)(g_y12 + (size_t)r * 512);
    const float4* y2 = y1 + 64;                       // columns [256,512) as float4
    float4* ao = (float4*)(out + (size_t)r * OUTA);
#pragma unroll
    for (int t = 0; t < 2; t++) {
        int idx = lane + t * 32;
        float4 a = y1[idx];
        float4 b = y2[idx];
        float4 o;
        o.x = s0 * a.x + s1 * b.x;
        o.y = s0 * a.y + s1 * b.y;
        o.z = s0 * a.z + s1 * b.z;
        o.w = s0 * a.w + s1 * b.w;
        ao[idx] = o;
    }
}

// =========================================================================
extern "C" void kernel_launch(void* const* d_in, const int* in_sizes, int n_in,
                              void* d_out, int out_size)
{
    const float* x   = (const float*)d_in[0];
    const float* W1  = (const float*)d_in[1];
    const float* W2  = (const float*)d_in[2];
    const float* A1  = (const float*)d_in[3];
    const float* b1  = (const float*)d_in[4];
    const float* c1  = (const float*)d_in[5];
    const float* A2  = (const float*)d_in[6];
    const float* b2  = (const float*)d_in[7];
    const float* c2  = (const float*)d_in[8];
    const float* Wc1 = (const float*)d_in[9];
    const float* bc1 = (const float*)d_in[10];
    const float* Wc2 = (const float*)d_in[11];
    const float* bc2 = (const float*)d_in[12];
    float* out = (float*)d_out;

    gemm_w_kernel<<<dim3(N_W / BN, BATCH / BM), 256>>>(x, W1, W2, Wc1);
    gemm_a_kernel<<<dim3(N_A / BN, BATCH / BM), 256>>>(x, A1, A2);
    epilogue_kernel<<<BATCH / 8, 256>>>(x, b1, c1, b2, c2, bc1, Wc2, bc2, out);
}

// round 3
// speedup vs baseline: 3.1715x; 3.1715x over previous
#include <cuda_runtime.h>
#include <cstdint>
#include <math.h>

#define BATCH   65536
#define KDIM    512
#define OUTA    256
#define HID     64
#define NB      1664            // packed B rows: 13 tiles of 128

// ---------------- scratch (static device globals) ------------------------
__device__ float g_B[(size_t)NB * KDIM];         // packed K-major B (tf32-rounded)
__device__ float g_y12[(size_t)BATCH * 512];     // y1 | y2
__device__ float g_h[(size_t)BATCH * HID];       // chooser pre-activation
__device__ float g_xb1[BATCH];
__device__ float g_xb2[BATCH];
__device__ float g_qpart[8][BATCH];              // q1: 0..3, q2: 4..7

// ======================= helpers ==========================================
__device__ __forceinline__ uint32_t f2tf32(float f) {
    uint32_t r;
    asm("cvt.rna.tf32.f32 %0, %1;" : "=r"(r) : "f"(f));
    return r;
}
__device__ __forceinline__ uint32_t smem_u32(const void* p) {
    uint32_t a;
    asm("{ .reg .u64 t; cvta.to.shared.u64 t, %1; cvt.u32.u64 %0, t; }" : "=r"(a) : "l"(p));
    return a;
}
#define CP_ASYNC16(dst, src) \
    asm volatile("cp.async.cg.shared.global [%0], [%1], 16;" :: "r"(dst), "l"(src))
#define CP_COMMIT() asm volatile("cp.async.commit_group;" ::: "memory")
#define CP_WAIT(n)  asm volatile("cp.async.wait_group %0;" :: "n"(n) : "memory")

__device__ __forceinline__ void mma_tf32(float* c, const uint32_t* a, const uint32_t* b) {
    asm volatile(
        "mma.sync.aligned.m16n8k8.row.col.f32.tf32.tf32.f32 "
        "{%0,%1,%2,%3}, {%4,%5,%6,%7}, {%8,%9}, {%0,%1,%2,%3};"
        : "+f"(c[0]), "+f"(c[1]), "+f"(c[2]), "+f"(c[3])
        : "r"(a[0]), "r"(a[1]), "r"(a[2]), "r"(a[3]), "r"(b[0]), "r"(b[1]));
}

// ======================= pack kernel ======================================
// g_B rows: [0,256)=W1, [256,512)=W2, [512,576)=Wc1, 576=b1, 577=b2,
// [578,640)=zero, [640,1152)=A1^T, [1152,1664)=A2^T.  Values tf32-rounded.
__global__ __launch_bounds__(512) void pack_kernel(
    const float* __restrict__ W1, const float* __restrict__ W2,
    const float* __restrict__ Wc1,
    const float* __restrict__ b1, const float* __restrict__ b2,
    const float* __restrict__ A1, const float* __restrict__ A2)
{
    size_t idx = (size_t)blockIdx.x * blockDim.x + threadIdx.x;
    if (idx >= (size_t)NB * KDIM) return;
    int row = (int)(idx >> 9);
    int k   = (int)(idx & 511);
    float v;
    if      (row < 256)  v = W1[(size_t)row * KDIM + k];
    else if (row < 512)  v = W2[(size_t)(row - 256) * KDIM + k];
    else if (row < 576)  v = Wc1[(size_t)(row - 512) * KDIM + k];
    else if (row == 576) v = b1[k];
    else if (row == 577) v = b2[k];
    else if (row < 640)  v = 0.f;
    else if (row < 1152) v = A1[(size_t)k * KDIM + (row - 640)];
    else                 v = A2[(size_t)k * KDIM + (row - 1152)];
    g_B[idx] = __uint_as_float(f2tf32(v));
}

// ======================= tf32 mma.sync GEMM ===============================
// C[B,1664] = x @ g_B^T.  CTA tile 128x128, warp tile 64x32, K-chunk 32.
#define ALD 36                                 // smem row stride (floats)
#define STAGE_BYTES (2 * 128 * ALD * 4)        // A + B per stage = 36864
#define SMEM_BYTES  (2 * STAGE_BYTES)          // 73728

__global__ __launch_bounds__(256, 2) void gemm_tc_kernel(const float* __restrict__ x)
{
    extern __shared__ char smem[];
    const uint32_t sbase = smem_u32(smem);
    const int tid   = threadIdx.x;
    const int wid   = tid >> 5;
    const int lane  = tid & 31;
    const int nblk  = blockIdx.x;              // 0..12
    const int row0  = blockIdx.y * 128;
    const int colbase = nblk * 128;

    const int warp_m = wid & 1;                // 2 row groups of 64
    const int warp_n = wid >> 1;               // 4 col groups of 32
    const int lq  = lane >> 2;                 // 0..7
    const int lr  = lane & 3;                  // 0..3

    // stage s: A at s*STAGE_BYTES, B at s*STAGE_BYTES + 128*ALD*4
    const int ldrow  = tid >> 3;               // 0..31 per 256-lin chunk? (see below)
    const int ldslot = tid & 7;

    // ---------------- async chunk loader ----------------
    auto load_chunk = [&](int stage, int k0) {
        uint32_t aoff = sbase + stage * STAGE_BYTES;
        uint32_t boff = aoff + 128 * ALD * 4;
#pragma unroll
        for (int i = 0; i < 4; i++) {
            int lin  = tid + i * 256;          // 0..1023
            int row  = lin >> 3;               // 0..127
            int slot = lin & 7;                // 0..7
            const float* src = x + (size_t)(row0 + row) * KDIM + k0 + slot * 4;
            CP_ASYNC16(aoff + row * (ALD * 4) + slot * 16, src);
        }
#pragma unroll
        for (int i = 0; i < 4; i++) {
            int lin  = tid + i * 256;
            int row  = lin >> 3;
            int slot = lin & 7;
            const float* src = g_B + (size_t)(colbase + row) * KDIM + k0 + slot * 4;
            CP_ASYNC16(boff + row * (ALD * 4) + slot * 16, src);
        }
    };

    float acc[4][4][4];
#pragma unroll
    for (int mt = 0; mt < 4; mt++)
#pragma unroll
        for (int nt = 0; nt < 4; nt++)
#pragma unroll
            for (int i = 0; i < 4; i++) acc[mt][nt][i] = 0.f;

    load_chunk(0, 0);
    CP_COMMIT();

    for (int ch = 0; ch < 16; ch++) {
        const int stage = ch & 1;
        if (ch < 15) {
            load_chunk(stage ^ 1, (ch + 1) * 32);
            CP_COMMIT();
            CP_WAIT(1);
        } else {
            CP_WAIT(0);
        }
        __syncthreads();

        const float* As = (const float*)(smem + stage * STAGE_BYTES);
        const float* Bs = (const float*)(smem + stage * STAGE_BYTES + 128 * ALD * 4);

#pragma unroll
        for (int kk = 0; kk < 4; kk++) {
            const int kc = kk * 8 + lr;
            uint32_t af[4][4];
#pragma unroll
            for (int mt = 0; mt < 4; mt++) {
                const int r = warp_m * 64 + mt * 16 + lq;
                af[mt][0] = f2tf32(As[r * ALD + kc]);
                af[mt][1] = f2tf32(As[(r + 8) * ALD + kc]);
                af[mt][2] = f2tf32(As[r * ALD + kc + 4]);
                af[mt][3] = f2tf32(As[(r + 8) * ALD + kc + 4]);
            }
            uint32_t bf[4][2];
#pragma unroll
            for (int nt = 0; nt < 4; nt++) {
                const int n = warp_n * 32 + nt * 8 + lq;
                bf[nt][0] = __float_as_uint(Bs[n * ALD + kc]);
                bf[nt][1] = __float_as_uint(Bs[n * ALD + kc + 4]);
            }
#pragma unroll
            for (int mt = 0; mt < 4; mt++)
#pragma unroll
                for (int nt = 0; nt < 4; nt++)
                    mma_tf32(acc[mt][nt], af[mt], bf[nt]);
        }
        __syncthreads();
    }

    // =================== fused epilogue ===================================
    // C element map: acc[mt][nt][0..3]:
    //   rows: rA = row0 + warp_m*64 + mt*16 + lq,  rB = rA + 8
    //   cols: c0 = colgrp + 2*lr, c1 = c0+1  (colgrp = warp_n*32 + nt*8)
    if (nblk < 4) {
        // y1|y2 tiles -> g_y12 cols nblk*128 + ...
#pragma unroll
        for (int mt = 0; mt < 4; mt++) {
            const int rA = row0 + warp_m * 64 + mt * 16 + lq;
#pragma unroll
            for (int nt = 0; nt < 4; nt++) {
                const int c = nblk * 128 + warp_n * 32 + nt * 8 + 2 * lr;
                *(float2*)(g_y12 + (size_t)rA * 512 + c) =
                    make_float2(acc[mt][nt][0], acc[mt][nt][1]);
                *(float2*)(g_y12 + (size_t)(rA + 8) * 512 + c) =
                    make_float2(acc[mt][nt][2], acc[mt][nt][3]);
            }
        }
    } else if (nblk == 4) {
        // local col lc = warp_n*32 + nt*8 + 2*lr; lc<64 -> h; lc==64 -> xb1/xb2
#pragma unroll
        for (int mt = 0; mt < 4; mt++) {
            const int rA = row0 + warp_m * 64 + mt * 16 + lq;
            if (warp_n < 2) {
#pragma unroll
                for (int nt = 0; nt < 4; nt++) {
                    const int lc = warp_n * 32 + nt * 8 + 2 * lr;
                    *(float2*)(g_h + (size_t)rA * HID + lc) =
                        make_float2(acc[mt][nt][0], acc[mt][nt][1]);
                    *(float2*)(g_h + (size_t)(rA + 8) * HID + lc) =
                        make_float2(acc[mt][nt][2], acc[mt][nt][3]);
                }
            } else if (warp_n == 2 && lr == 0) {
                // lc==64 -> cols 576 (b1), 577 (b2) of packed B
                g_xb1[rA]     = acc[mt][0][0];
                g_xb2[rA]     = acc[mt][0][1];
                g_xb1[rA + 8] = acc[mt][0][2];
                g_xb2[rA + 8] = acc[mt][0][3];
            }
        }
    } else {
        // quadratic tiles: row-dot with x, fused.
        const int qt = nblk - 5;                       // 0..7
        const int jbase = (qt < 4 ? qt : qt - 4) * 128;// col offset within A (0..511)
        float p[4][2];
#pragma unroll
        for (int mt = 0; mt < 4; mt++) { p[mt][0] = 0.f; p[mt][1] = 0.f; }
#pragma unroll
        for (int mt = 0; mt < 4; mt++) {
            const int rA = row0 + warp_m * 64 + mt * 16 + lq;
#pragma unroll
            for (int nt = 0; nt < 4; nt++) {
                const int j = jbase + warp_n * 32 + nt * 8 + 2 * lr;
                const float2 x0 = __ldg((const float2*)(x + (size_t)rA * KDIM + j));
                const float2 x1 = __ldg((const float2*)(x + (size_t)(rA + 8) * KDIM + j));
                p[mt][0] = fmaf(acc[mt][nt][0], x0.x, fmaf(acc[mt][nt][1], x0.y, p[mt][0]));
                p[mt][1] = fmaf(acc[mt][nt][2], x1.x, fmaf(acc[mt][nt][3], x1.y, p[mt][1]));
            }
        }
        // reduce across the 4 lanes of each quad (they hold disjoint cols of same row)
#pragma unroll
        for (int mt = 0; mt < 4; mt++) {
#pragma unroll
            for (int h = 0; h < 2; h++) {
                p[mt][h] += __shfl_xor_sync(0xffffffffu, p[mt][h], 1);
                p[mt][h] += __shfl_xor_sync(0xffffffffu, p[mt][h], 2);
            }
        }
        __syncthreads();                    // smem free -> reuse as reduction buf
        float* red = (float*)smem;          // [128][4]
        if (lr == 0) {
#pragma unroll
            for (int mt = 0; mt < 4; mt++) {
                const int rl = warp_m * 64 + mt * 16 + lq;
                red[rl * 4 + warp_n]       = p[mt][0];
                red[(rl + 8) * 4 + warp_n] = p[mt][1];
            }
        }
        __syncthreads();
        if (tid < 128) {
            float s = red[tid * 4] + red[tid * 4 + 1] + red[tid * 4 + 2] + red[tid * 4 + 3];
            g_qpart[qt][row0 + tid] = s;
        }
    }
}

// ======================= final epilogue ===================================
__global__ __launch_bounds__(256) void final_kernel(
    const float* __restrict__ c1, const float* __restrict__ c2,
    const float* __restrict__ bc1,
    const float* __restrict__ Wc2, const float* __restrict__ bc2,
    float* __restrict__ out)
{
    const int warp = threadIdx.x >> 5;
    const int lane = threadIdx.x & 31;
    const int r = blockIdx.x * 8 + warp;

    // chooser: relu(h + bc1) @ Wc2^T + bc2 -> sigmoid
    float p0 = 0.f, p1 = 0.f;
#pragma unroll
    for (int t = 0; t < 2; t++) {
        int j = lane * 2 + t;
        float h = g_h[(size_t)r * HID + j] + bc1[j];
        h = fmaxf(h, 0.f);
        p0 = fmaf(h, Wc2[j],      p0);
        p1 = fmaf(h, Wc2[64 + j], p1);
    }
#pragma unroll
    for (int o = 16; o; o >>= 1) {
        p0 += __shfl_xor_sync(0xffffffffu, p0, o);
        p1 += __shfl_xor_sync(0xffffffffu, p1, o);
    }
    float s0 = 1.f / (1.f + expf(-(p0 + bc2[0])));
    float s1 = 1.f / (1.f + expf(-(p1 + bc2[1])));

    if (lane == 0) {
        float q1 = g_qpart[0][r] + g_qpart[1][r] + g_qpart[2][r] + g_qpart[3][r]
                 + g_xb1[r] + c1[0];
        float q2 = g_qpart[4][r] + g_qpart[5][r] + g_qpart[6][r] + g_qpart[7][r]
                 + g_xb2[r] + c2[0];
        out[(size_t)BATCH * OUTA + r] = s0 * q1 + s1 * q2;
    }

    const float4* y1 = (const float4*)(g_y12 + (size_t)r * 512);
    const float4* y2 = y1 + 64;
    float4* ao = (float4*)(out + (size_t)r * OUTA);
#pragma unroll
    for (int t = 0; t < 2; t++) {
        int idx = lane + t * 32;
        float4 a = y1[idx];
        float4 b = y2[idx];
        ao[idx] = make_float4(s0 * a.x + s1 * b.x, s0 * a.y + s1 * b.y,
                              s0 * a.z + s1 * b.z, s0 * a.w + s1 * b.w);
    }
}

// =========================================================================
extern "C" void kernel_launch(void* const* d_in, const int* in_sizes, int n_in,
                              void* d_out, int out_size)
{
    const float* x   = (const float*)d_in[0];
    const float* W1  = (const float*)d_in[1];
    const float* W2  = (const float*)d_in[2];
    const float* A1  = (const float*)d_in[3];
    const float* b1  = (const float*)d_in[4];
    const float* c1  = (const float*)d_in[5];
    const float* A2  = (const float*)d_in[6];
    const float* b2  = (const float*)d_in[7];
    const float* c2  = (const float*)d_in[8];
    const float* Wc1 = (const float*)d_in[9];
    const float* bc1 = (const float*)d_in[10];
    const float* Wc2 = (const float*)d_in[11];
    const float* bc2 = (const float*)d_in[12];
    float* out = (float*)d_out;

    cudaFuncSetAttribute(gemm_tc_kernel,
                         cudaFuncAttributeMaxDynamicSharedMemorySize, SMEM_BYTES);

    pack_kernel<<<(NB * KDIM + 511) / 512, 512>>>(W1, W2, Wc1, b1, b2, A1, A2);
    gemm_tc_kernel<<<dim3(13, BATCH / 128), 256, SMEM_BYTES>>>(x);
    final_kernel<<<BATCH / 8, 256>>>(c1, c2, bc1, Wc2, bc2, out);
}

// round 4
// speedup vs baseline: 6.7552x; 2.1300x over previous
#include <cuda_runtime.h>
#include <cuda_fp16.h>
#include <cstdint>
#include <math.h>

#define BATCH   65536
#define KDIM    512
#define OUTA    256
#define HID     64
#define NB      1664            // packed B rows: 13 tiles of 128

// ---------------- scratch (static device globals) ------------------------
__device__ __half g_Bh[(size_t)NB * KDIM];       // packed B (fp16)
__device__ __half g_X[(size_t)BATCH * KDIM];     // x (fp16)
__device__ float  g_y12[(size_t)BATCH * 512];    // y1 | y2
__device__ float  g_h[(size_t)BATCH * HID];      // chooser pre-activation
__device__ float  g_xb1[BATCH];
__device__ float  g_xb2[BATCH];
__device__ float  g_qpart[8][BATCH];             // q1: 0..3, q2: 4..7

// ======================= helpers ==========================================
__device__ __forceinline__ uint32_t smem_u32(const void* p) {
    uint32_t a;
    asm("{ .reg .u64 t; cvta.to.shared.u64 t, %1; cvt.u32.u64 %0, t; }" : "=r"(a) : "l"(p));
    return a;
}
#define CP_ASYNC16(dst, src) \
    asm volatile("cp.async.cg.shared.global [%0], [%1], 16;" :: "r"(dst), "l"(src))
#define CP_COMMIT() asm volatile("cp.async.commit_group;" ::: "memory")
#define CP_WAIT(n)  asm volatile("cp.async.wait_group %0;" :: "n"(n) : "memory")

__device__ __forceinline__ void ldmatrix_x4(uint32_t& r0, uint32_t& r1,
                                            uint32_t& r2, uint32_t& r3, uint32_t addr) {
    asm volatile("ldmatrix.sync.aligned.m8n8.x4.shared.b16 {%0,%1,%2,%3}, [%4];"
        : "=r"(r0), "=r"(r1), "=r"(r2), "=r"(r3) : "r"(addr));
}
__device__ __forceinline__ void mma_f16(float* c, const uint32_t* a, const uint32_t* b) {
    asm volatile(
        "mma.sync.aligned.m16n8k16.row.col.f32.f16.f16.f32 "
        "{%0,%1,%2,%3}, {%4,%5,%6,%7}, {%8,%9}, {%0,%1,%2,%3};"
        : "+f"(c[0]), "+f"(c[1]), "+f"(c[2]), "+f"(c[3])
        : "r"(a[0]), "r"(a[1]), "r"(a[2]), "r"(a[3]), "r"(b[0]), "r"(b[1]));
}

// ======================= pack kernels =====================================
// g_Bh rows: [0,256)=W1, [256,512)=W2, [512,576)=Wc1, 576=b1, 577=b2,
// [578,640)=zero, [640,1152)=A1^T, [1152,1664)=A2^T.
__global__ __launch_bounds__(512) void pack_b_kernel(
    const float* __restrict__ W1, const float* __restrict__ W2,
    const float* __restrict__ Wc1,
    const float* __restrict__ b1, const float* __restrict__ b2,
    const float* __restrict__ A1, const float* __restrict__ A2)
{
    size_t idx = (size_t)blockIdx.x * blockDim.x + threadIdx.x;
    if (idx >= (size_t)NB * KDIM) return;
    int row = (int)(idx >> 9);
    int k   = (int)(idx & 511);
    float v;
    if      (row < 256)  v = W1[(size_t)row * KDIM + k];
    else if (row < 512)  v = W2[(size_t)(row - 256) * KDIM + k];
    else if (row < 576)  v = Wc1[(size_t)(row - 512) * KDIM + k];
    else if (row == 576) v = b1[k];
    else if (row == 577) v = b2[k];
    else if (row < 640)  v = 0.f;
    else if (row < 1152) v = A1[(size_t)k * KDIM + (row - 640)];
    else                 v = A2[(size_t)k * KDIM + (row - 1152)];
    g_Bh[idx] = __float2half_rn(v);
}

__global__ __launch_bounds__(256) void pack_x_kernel(const float* __restrict__ x)
{
    size_t i = (size_t)blockIdx.x * blockDim.x + threadIdx.x;   // float4 index
    float4 v = __ldg((const float4*)x + i);
    __half2 h0 = __floats2half2_rn(v.x, v.y);
    __half2 h1 = __floats2half2_rn(v.z, v.w);
    uint2 u;
    u.x = *(uint32_t*)&h0;
    u.y = *(uint32_t*)&h1;
    ((uint2*)g_X)[i] = u;
}

// ======================= fp16 mma.sync GEMM ===============================
// C[B,1664] = X @ g_Bh^T.  CTA tile 128x128, warp tile 64x32, K-chunk 64.
// Smem per stage: A 128x64 halves (16KB) + B 128x64 (16KB). 2 stages = 64KB.
// Layout: row-major, 128B/row; 16B chunk c stored at (c ^ (row&7)).
#define STAGE_BYTES 32768
#define SMEM_BYTES  (2 * STAGE_BYTES)

__global__ __launch_bounds__(256, 2) void gemm_tc_kernel(const float* __restrict__ x)
{
    extern __shared__ char smem[];
    const uint32_t sbase = smem_u32(smem);
    const int tid   = threadIdx.x;
    const int wid   = tid >> 5;
    const int lane  = tid & 31;
    const int nblk  = blockIdx.x;              // 0..12
    const int row0  = blockIdx.y * 128;
    const int colbase = nblk * 128;

    const int warp_m = wid & 1;                // 2 row groups of 64
    const int warp_n = wid >> 1;               // 4 col groups of 32
    const int lq  = lane >> 2;                 // 0..7
    const int lr  = lane & 3;                  // 0..3
    const int t8  = lane >> 3;                 // ldmatrix tile id 0..3
    const int r8  = lane & 7;

    // ---------------- async chunk loader (k-chunk = 64 halves = 128B) -----
    auto load_chunk = [&](int stage, int k0) {
        uint32_t abase = sbase + stage * STAGE_BYTES;
        uint32_t bbase = abase + 16384;
#pragma unroll
        for (int i = 0; i < 4; i++) {
            int lin = tid + i * 256;           // 0..1023
            int row = lin >> 3;                // 0..127
            int c   = lin & 7;                 // 16B chunk 0..7
            const __half* src = g_X + (size_t)(row0 + row) * KDIM + k0 + c * 8;
            CP_ASYNC16(abase + row * 128 + ((c ^ (row & 7)) << 4), src);
        }
#pragma unroll
        for (int i = 0; i < 4; i++) {
            int lin = tid + i * 256;
            int row = lin >> 3;
            int c   = lin & 7;
            const __half* src = g_Bh + (size_t)(colbase + row) * KDIM + k0 + c * 8;
            CP_ASYNC16(bbase + row * 128 + ((c ^ (row & 7)) << 4), src);
        }
    };

    float acc[4][4][4];
#pragma unroll
    for (int mt = 0; mt < 4; mt++)
#pragma unroll
        for (int nt = 0; nt < 4; nt++)
#pragma unroll
            for (int i = 0; i < 4; i++) acc[mt][nt][i] = 0.f;

    load_chunk(0, 0);
    CP_COMMIT();

    for (int ch = 0; ch < 8; ch++) {
        const int stage = ch & 1;
        if (ch < 7) {
            load_chunk(stage ^ 1, (ch + 1) * 64);
            CP_COMMIT();
            CP_WAIT(1);
        } else {
            CP_WAIT(0);
        }
        __syncthreads();

        const uint32_t abase = sbase + stage * STAGE_BYTES;
        const uint32_t bbase = abase + 16384;

#pragma unroll
        for (int kk = 0; kk < 4; kk++) {       // 4 x k16 per chunk
            // A fragments: 4 x ldmatrix.x4  (m16 x k16 each)
            uint32_t af[4][4];
#pragma unroll
            for (int mt = 0; mt < 4; mt++) {
                int arow = warp_m * 64 + mt * 16 + ((t8 & 1) << 3) + r8;
                int ac   = kk * 2 + (t8 >> 1);
                uint32_t addr = abase + arow * 128 + ((ac ^ (arow & 7)) << 4);
                ldmatrix_x4(af[mt][0], af[mt][1], af[mt][2], af[mt][3], addr);
            }
            // B fragments: 2 x ldmatrix.x4  (n16 x k16 each -> 2 nt)
            uint32_t bf[4][2];
#pragma unroll
            for (int nt2 = 0; nt2 < 2; nt2++) {
                int brow = warp_n * 32 + nt2 * 16 + ((t8 >> 1) << 3) + r8;
                int bc   = kk * 2 + (t8 & 1);
                uint32_t addr = bbase + brow * 128 + ((bc ^ (brow & 7)) << 4);
                ldmatrix_x4(bf[nt2 * 2][0], bf[nt2 * 2][1],
                            bf[nt2 * 2 + 1][0], bf[nt2 * 2 + 1][1], addr);
            }
#pragma unroll
            for (int mt = 0; mt < 4; mt++)
#pragma unroll
                for (int nt = 0; nt < 4; nt++)
                    mma_f16(acc[mt][nt], af[mt], bf[nt]);
        }
        __syncthreads();
    }

    // =================== fused epilogue ===================================
    // acc[mt][nt][0..3]: rows rA = row0+warp_m*64+mt*16+lq, rB = rA+8;
    // cols c0 = warp_n*32+nt*8+2*lr, c1 = c0+1.
    if (nblk < 4) {
#pragma unroll
        for (int mt = 0; mt < 4; mt++) {
            const int rA = row0 + warp_m * 64 + mt * 16 + lq;
#pragma unroll
            for (int nt = 0; nt < 4; nt++) {
                const int c = nblk * 128 + warp_n * 32 + nt * 8 + 2 * lr;
                *(float2*)(g_y12 + (size_t)rA * 512 + c) =
                    make_float2(acc[mt][nt][0], acc[mt][nt][1]);
                *(float2*)(g_y12 + (size_t)(rA + 8) * 512 + c) =
                    make_float2(acc[mt][nt][2], acc[mt][nt][3]);
            }
        }
    } else if (nblk == 4) {
#pragma unroll
        for (int mt = 0; mt < 4; mt++) {
            const int rA = row0 + warp_m * 64 + mt * 16 + lq;
            if (warp_n < 2) {
#pragma unroll
                for (int nt = 0; nt < 4; nt++) {
                    const int lc = warp_n * 32 + nt * 8 + 2 * lr;
                    *(float2*)(g_h + (size_t)rA * HID + lc) =
                        make_float2(acc[mt][nt][0], acc[mt][nt][1]);
                    *(float2*)(g_h + (size_t)(rA + 8) * HID + lc) =
                        make_float2(acc[mt][nt][2], acc[mt][nt][3]);
                }
            } else if (warp_n == 2 && lr == 0) {
                g_xb1[rA]     = acc[mt][0][0];
                g_xb2[rA]     = acc[mt][0][1];
                g_xb1[rA + 8] = acc[mt][0][2];
                g_xb2[rA + 8] = acc[mt][0][3];
            }
        }
    } else {
        // quadratic tiles: fused row-dot with x
        const int qt = nblk - 5;                        // 0..7
        const int jbase = (qt < 4 ? qt : qt - 4) * 128; // col offset within A
        float p[4][2];
#pragma unroll
        for (int mt = 0; mt < 4; mt++) { p[mt][0] = 0.f; p[mt][1] = 0.f; }
#pragma unroll
        for (int mt = 0; mt < 4; mt++) {
            const int rA = row0 + warp_m * 64 + mt * 16 + lq;
#pragma unroll
            for (int nt = 0; nt < 4; nt++) {
                const int j = jbase + warp_n * 32 + nt * 8 + 2 * lr;
                const float2 x0 = __ldg((const float2*)(x + (size_t)rA * KDIM + j));
                const float2 x1 = __ldg((const float2*)(x + (size_t)(rA + 8) * KDIM + j));
                p[mt][0] = fmaf(acc[mt][nt][0], x0.x, fmaf(acc[mt][nt][1], x0.y, p[mt][0]));
                p[mt][1] = fmaf(acc[mt][nt][2], x1.x, fmaf(acc[mt][nt][3], x1.y, p[mt][1]));
            }
        }
#pragma unroll
        for (int mt = 0; mt < 4; mt++) {
#pragma unroll
            for (int h = 0; h < 2; h++) {
                p[mt][h] += __shfl_xor_sync(0xffffffffu, p[mt][h], 1);
                p[mt][h] += __shfl_xor_sync(0xffffffffu, p[mt][h], 2);
            }
        }
        __syncthreads();
        float* red = (float*)smem;                      // [128][4]
        if (lr == 0) {
#pragma unroll
            for (int mt = 0; mt < 4; mt++) {
                const int rl = warp_m * 64 + mt * 16 + lq;
                red[rl * 4 + warp_n]       = p[mt][0];
                red[(rl + 8) * 4 + warp_n] = p[mt][1];
            }
        }
        __syncthreads();
        if (tid < 128) {
            float s = red[tid * 4] + red[tid * 4 + 1] + red[tid * 4 + 2] + red[tid * 4 + 3];
            g_qpart[qt][row0 + tid] = s;
        }
    }
}

// ======================= final epilogue ===================================
__global__ __launch_bounds__(256) void final_kernel(
    const float* __restrict__ c1, const float* __restrict__ c2,
    const float* __restrict__ bc1,
    const float* __restrict__ Wc2, const float* __restrict__ bc2,
    float* __restrict__ out)
{
    const int warp = threadIdx.x >> 5;
    const int lane = threadIdx.x & 31;
    const int r = blockIdx.x * 8 + warp;

    float p0 = 0.f, p1 = 0.f;
#pragma unroll
    for (int t = 0; t < 2; t++) {
        int j = lane * 2 + t;
        float h = g_h[(size_t)r * HID + j] + bc1[j];
        h = fmaxf(h, 0.f);
        p0 = fmaf(h, Wc2[j],      p0);
        p1 = fmaf(h, Wc2[64 + j], p1);
    }
#pragma unroll
    for (int o = 16; o; o >>= 1) {
        p0 += __shfl_xor_sync(0xffffffffu, p0, o);
        p1 += __shfl_xor_sync(0xffffffffu, p1, o);
    }
    float s0 = 1.f / (1.f + expf(-(p0 + bc2[0])));
    float s1 = 1.f / (1.f + expf(-(p1 + bc2[1])));

    if (lane == 0) {
        float q1 = g_qpart[0][r] + g_qpart[1][r] + g_qpart[2][r] + g_qpart[3][r]
                 + g_xb1[r] + c1[0];
        float q2 = g_qpart[4][r] + g_qpart[5][r] + g_qpart[6][r] + g_qpart[7][r]
                 + g_xb2[r] + c2[0];
        out[(size_t)BATCH * OUTA + r] = s0 * q1 + s1 * q2;
    }

    const float4* y1 = (const float4*)(g_y12 + (size_t)r * 512);
    const float4* y2 = y1 + 64;
    float4* ao = (float4*)(out + (size_t)r * OUTA);
#pragma unroll
    for (int t = 0; t < 2; t++) {
        int idx = lane + t * 32;
        float4 a = y1[idx];
        float4 b = y2[idx];
        ao[idx] = make_float4(s0 * a.x + s1 * b.x, s0 * a.y + s1 * b.y,
                              s0 * a.z + s1 * b.z, s0 * a.w + s1 * b.w);
    }
}

// =========================================================================
extern "C" void kernel_launch(void* const* d_in, const int* in_sizes, int n_in,
                              void* d_out, int out_size)
{
    const float* x   = (const float*)d_in[0];
    const float* W1  = (const float*)d_in[1];
    const float* W2  = (const float*)d_in[2];
    const float* A1  = (const float*)d_in[3];
    const float* b1  = (const float*)d_in[4];
    const float* c1  = (const float*)d_in[5];
    const float* A2  = (const float*)d_in[6];
    const float* b2  = (const float*)d_in[7];
    const float* c2  = (const float*)d_in[8];
    const float* Wc1 = (const float*)d_in[9];
    const float* bc1 = (const float*)d_in[10];
    const float* Wc2 = (const float*)d_in[11];
    const float* bc2 = (const float*)d_in[12];
    float* out = (float*)d_out;

    cudaFuncSetAttribute(gemm_tc_kernel,
                         cudaFuncAttributeMaxDynamicSharedMemorySize, SMEM_BYTES);

    pack_b_kernel<<<(NB * KDIM + 511) / 512, 512>>>(W1, W2, Wc1, b1, b2, A1, A2);
    pack_x_kernel<<<(BATCH * KDIM / 4) / 256, 256>>>(x);
    gemm_tc_kernel<<<dim3(13, BATCH / 128), 256, SMEM_BYTES>>>(x);
    final_kernel<<<BATCH / 8, 256>>>(c1, c2, bc1, Wc2, bc2, out);
}

// round 5
// speedup vs baseline: 7.0955x; 1.0504x over previous
#include <cuda_runtime.h>
#include <cuda_fp16.h>
#include <cstdint>
#include <math.h>

#define BATCH   65536
#define KDIM    512
#define OUTA    256
#define HID     64
#define NB      1664            // packed B rows: 13 tiles of 128

// ---------------- scratch (static device globals) ------------------------
__device__ __half g_Bh[(size_t)NB * KDIM];       // packed B (fp16)
__device__ __half g_X[(size_t)BATCH * KDIM];     // x (fp16)
__device__ float  g_h[(size_t)BATCH * HID];      // chooser pre-activation
__device__ float  g_xb1[BATCH];
__device__ float  g_xb2[BATCH];
__device__ float2 g_sig[BATCH];                  // (s0, s1)
__device__ float  g_qpart[8][BATCH];             // q1: 0..3, q2: 4..7

// ======================= helpers ==========================================
__device__ __forceinline__ uint32_t smem_u32(const void* p) {
    uint32_t a;
    asm("{ .reg .u64 t; cvta.to.shared.u64 t, %1; cvt.u32.u64 %0, t; }" : "=r"(a) : "l"(p));
    return a;
}
#define CP_ASYNC16(dst, src) \
    asm volatile("cp.async.cg.shared.global [%0], [%1], 16;" :: "r"(dst), "l"(src))
#define CP_COMMIT() asm volatile("cp.async.commit_group;" ::: "memory")
#define CP_WAIT(n)  asm volatile("cp.async.wait_group %0;" :: "n"(n) : "memory")

__device__ __forceinline__ void ldmatrix_x4(uint32_t& r0, uint32_t& r1,
                                            uint32_t& r2, uint32_t& r3, uint32_t addr) {
    asm volatile("ldmatrix.sync.aligned.m8n8.x4.shared.b16 {%0,%1,%2,%3}, [%4];"
        : "=r"(r0), "=r"(r1), "=r"(r2), "=r"(r3) : "r"(addr));
}
__device__ __forceinline__ void mma_f16(float* c, const uint32_t* a, const uint32_t* b) {
    asm volatile(
        "mma.sync.aligned.m16n8k16.row.col.f32.f16.f16.f32 "
        "{%0,%1,%2,%3}, {%4,%5,%6,%7}, {%8,%9}, {%0,%1,%2,%3};"
        : "+f"(c[0]), "+f"(c[1]), "+f"(c[2]), "+f"(c[3])
        : "r"(a[0]), "r"(a[1]), "r"(a[2]), "r"(a[3]), "r"(b[0]), "r"(b[1]));
}

// ======================= pack kernels =====================================
// g_Bh rows: [0,512) = interleaved W1/W2 (2j=W1_j, 2j+1=W2_j)  -> tiles 0..3
//            [512,576)=Wc1, 576=b1, 577=b2, [578,640)=0        -> tile 4
//            [640,1152)=A1^T, [1152,1664)=A2^T                 -> tiles 5..12
__global__ __launch_bounds__(512) void pack_b_kernel(
    const float* __restrict__ W1, const float* __restrict__ W2,
    const float* __restrict__ Wc1,
    const float* __restrict__ b1, const float* __restrict__ b2,
    const float* __restrict__ A1, const float* __restrict__ A2)
{
    size_t idx = (size_t)blockIdx.x * blockDim.x + threadIdx.x;
    if (idx >= (size_t)NB * KDIM) return;
    int row = (int)(idx >> 9);
    int k   = (int)(idx & 511);
    float v;
    if (row < 512) {
        int j = row >> 1;
        v = (row & 1) ? W2[(size_t)j * KDIM + k] : W1[(size_t)j * KDIM + k];
    }
    else if (row < 576)  v = Wc1[(size_t)(row - 512) * KDIM + k];
    else if (row == 576) v = b1[k];
    else if (row == 577) v = b2[k];
    else if (row < 640)  v = 0.f;
    else if (row < 1152) v = A1[(size_t)k * KDIM + (row - 640)];
    else                 v = A2[(size_t)k * KDIM + (row - 1152)];
    g_Bh[idx] = __float2half_rn(v);
}

__global__ __launch_bounds__(256) void pack_x_kernel(const float* __restrict__ x)
{
    size_t i = (size_t)blockIdx.x * blockDim.x + threadIdx.x;   // float4 index
    float4 v = __ldg((const float4*)x + i);
    __half2 h0 = __floats2half2_rn(v.x, v.y);
    __half2 h1 = __floats2half2_rn(v.z, v.w);
    uint2 u;
    u.x = *(uint32_t*)&h0;
    u.y = *(uint32_t*)&h1;
    ((uint2*)g_X)[i] = u;
}

// ======================= sigma kernel =====================================
__global__ __launch_bounds__(256) void sigma_kernel(
    const float* __restrict__ bc1,
    const float* __restrict__ Wc2, const float* __restrict__ bc2)
{
    const int warp = threadIdx.x >> 5;
    const int lane = threadIdx.x & 31;
    const int r = blockIdx.x * 8 + warp;

    float p0 = 0.f, p1 = 0.f;
#pragma unroll
    for (int t = 0; t < 2; t++) {
        int j = lane * 2 + t;
        float h = g_h[(size_t)r * HID + j] + bc1[j];
        h = fmaxf(h, 0.f);
        p0 = fmaf(h, Wc2[j],      p0);
        p1 = fmaf(h, Wc2[64 + j], p1);
    }
#pragma unroll
    for (int o = 16; o; o >>= 1) {
        p0 += __shfl_xor_sync(0xffffffffu, p0, o);
        p1 += __shfl_xor_sync(0xffffffffu, p1, o);
    }
    if (lane == 0) {
        float s0 = 1.f / (1.f + expf(-(p0 + bc2[0])));
        float s1 = 1.f / (1.f + expf(-(p1 + bc2[1])));
        g_sig[r] = make_float2(s0, s1);
    }
}

// ======================= fp16 mma.sync GEMM ===============================
// CTA tile 128x128, warp tile 64x32, K-chunk 64, 3-stage cp.async pipeline.
#define STAGE_BYTES 32768
#define SMEM_BYTES  (3 * STAGE_BYTES)     // 98304

__global__ __launch_bounds__(256, 2) void gemm_tc_kernel(float* __restrict__ out, int mode)
{
    extern __shared__ char smem[];
    const uint32_t sbase = smem_u32(smem);
    const int tid   = threadIdx.x;
    const int wid   = tid >> 5;
    const int lane  = tid & 31;
    const int bx    = blockIdx.x;
    const int nblk  = mode ? (bx < 4 ? bx : bx + 1) : 4;
    const int row0  = blockIdx.y * 128;
    const int colbase = nblk * 128;

    const int warp_m = wid & 1;                // 2 row groups of 64
    const int warp_n = wid >> 1;               // 4 col groups of 32
    const int lq  = lane >> 2;                 // 0..7
    const int lr  = lane & 3;                  // 0..3
    const int t8  = lane >> 3;                 // ldmatrix tile id 0..3
    const int r8  = lane & 7;

    auto load_chunk = [&](int stage, int k0) {
        uint32_t abase = sbase + stage * STAGE_BYTES;
        uint32_t bbase = abase + 16384;
#pragma unroll
        for (int i = 0; i < 4; i++) {
            int lin = tid + i * 256;           // 0..1023
            int row = lin >> 3;                // 0..127
            int c   = lin & 7;                 // 16B chunk 0..7
            const __half* src = g_X + (size_t)(row0 + row) * KDIM + k0 + c * 8;
            CP_ASYNC16(abase + row * 128 + ((c ^ (row & 7)) << 4), src);
        }
#pragma unroll
        for (int i = 0; i < 4; i++) {
            int lin = tid + i * 256;
            int row = lin >> 3;
            int c   = lin & 7;
            const __half* src = g_Bh + (size_t)(colbase + row) * KDIM + k0 + c * 8;
            CP_ASYNC16(bbase + row * 128 + ((c ^ (row & 7)) << 4), src);
        }
    };

    float acc[4][4][4];
#pragma unroll
    for (int mt = 0; mt < 4; mt++)
#pragma unroll
        for (int nt = 0; nt < 4; nt++)
#pragma unroll
            for (int i = 0; i < 4; i++) acc[mt][nt][i] = 0.f;

    load_chunk(0, 0);  CP_COMMIT();
    load_chunk(1, 64); CP_COMMIT();

    for (int ch = 0; ch < 8; ch++) {
        const int stage = ch % 3;
        if (ch + 2 < 8) { load_chunk((ch + 2) % 3, (ch + 2) * 64); CP_COMMIT(); }
        if (ch < 6)      CP_WAIT(2);
        else if (ch == 6) CP_WAIT(1);
        else              CP_WAIT(0);
        __syncthreads();

        const uint32_t abase = sbase + stage * STAGE_BYTES;
        const uint32_t bbase = abase + 16384;

#pragma unroll
        for (int kk = 0; kk < 4; kk++) {       // 4 x k16 per chunk
            uint32_t af[4][4];
#pragma unroll
            for (int mt = 0; mt < 4; mt++) {
                int arow = warp_m * 64 + mt * 16 + ((t8 & 1) << 3) + r8;
                int ac   = kk * 2 + (t8 >> 1);
                uint32_t addr = abase + arow * 128 + ((ac ^ (arow & 7)) << 4);
                ldmatrix_x4(af[mt][0], af[mt][1], af[mt][2], af[mt][3], addr);
            }
            uint32_t bf[4][2];
#pragma unroll
            for (int nt2 = 0; nt2 < 2; nt2++) {
                int brow = warp_n * 32 + nt2 * 16 + ((t8 >> 1) << 3) + r8;
                int bc   = kk * 2 + (t8 & 1);
                uint32_t addr = bbase + brow * 128 + ((bc ^ (brow & 7)) << 4);
                ldmatrix_x4(bf[nt2 * 2][0], bf[nt2 * 2][1],
                            bf[nt2 * 2 + 1][0], bf[nt2 * 2 + 1][1], addr);
            }
#pragma unroll
            for (int mt = 0; mt < 4; mt++)
#pragma unroll
                for (int nt = 0; nt < 4; nt++)
                    mma_f16(acc[mt][nt], af[mt], bf[nt]);
        }
        __syncthreads();
    }

    // =================== fused epilogue ===================================
    // acc[mt][nt][0..3]: rows rA = row0+warp_m*64+mt*16+lq, rB = rA+8;
    // tile-local cols c0 = warp_n*32+nt*8+2*lr (even), c1 = c0+1.
    if (nblk < 4) {
        // interleaved W1/W2: (c0,c1) = (y1_j, y2_j), j = c0/2.
        // out[r][nblk*64 + j] = s0*y1_j + s1*y2_j
#pragma unroll
        for (int mt = 0; mt < 4; mt++) {
            const int rA = row0 + warp_m * 64 + mt * 16 + lq;
            const float2 sA = __ldg(&g_sig[rA]);
            const float2 sB = __ldg(&g_sig[rA + 8]);
#pragma unroll
            for (int nt = 0; nt < 4; nt++) {
                const int col = nblk * 64 + warp_n * 16 + nt * 4 + lr;
                out[(size_t)rA * OUTA + col] =
                    fmaf(sA.x, acc[mt][nt][0], sA.y * acc[mt][nt][1]);
                out[(size_t)(rA + 8) * OUTA + col] =
                    fmaf(sB.x, acc[mt][nt][2], sB.y * acc[mt][nt][3]);
            }
        }
    } else if (nblk == 4) {
        // chooser tile: local cols <64 -> g_h; col 64,65 -> xb1, xb2
#pragma unroll
        for (int mt = 0; mt < 4; mt++) {
            const int rA = row0 + warp_m * 64 + mt * 16 + lq;
            if (warp_n < 2) {
#pragma unroll
                for (int nt = 0; nt < 4; nt++) {
                    const int lc = warp_n * 32 + nt * 8 + 2 * lr;
                    *(float2*)(g_h + (size_t)rA * HID + lc) =
                        make_float2(acc[mt][nt][0], acc[mt][nt][1]);
                    *(float2*)(g_h + (size_t)(rA + 8) * HID + lc) =
                        make_float2(acc[mt][nt][2], acc[mt][nt][3]);
                }
            } else if (warp_n == 2 && lr == 0) {
                g_xb1[rA]     = acc[mt][0][0];
                g_xb2[rA]     = acc[mt][0][1];
                g_xb1[rA + 8] = acc[mt][0][2];
                g_xb2[rA + 8] = acc[mt][0][3];
            }
        }
    } else {
        // quadratic tiles: fused row-dot with fp16 x
        const int qt = nblk - 5;                        // 0..7
        const int jbase = (qt < 4 ? qt : qt - 4) * 128; // col offset within A
        float p[4][2];
#pragma unroll
        for (int mt = 0; mt < 4; mt++) { p[mt][0] = 0.f; p[mt][1] = 0.f; }
#pragma unroll
        for (int mt = 0; mt < 4; mt++) {
            const int rA = row0 + warp_m * 64 + mt * 16 + lq;
#pragma unroll
            for (int nt = 0; nt < 4; nt++) {
                const int j = jbase + warp_n * 32 + nt * 8 + 2 * lr;
                const __half2 h0 = __ldg((const __half2*)(g_X + (size_t)rA * KDIM + j));
                const __half2 h1 = __ldg((const __half2*)(g_X + (size_t)(rA + 8) * KDIM + j));
                const float2 x0 = __half22float2(h0);
                const float2 x1 = __half22float2(h1);
                p[mt][0] = fmaf(acc[mt][nt][0], x0.x, fmaf(acc[mt][nt][1], x0.y, p[mt][0]));
                p[mt][1] = fmaf(acc[mt][nt][2], x1.x, fmaf(acc[mt][nt][3], x1.y, p[mt][1]));
            }
        }
#pragma unroll
        for (int mt = 0; mt < 4; mt++) {
#pragma unroll
            for (int h = 0; h < 2; h++) {
                p[mt][h] += __shfl_xor_sync(0xffffffffu, p[mt][h], 1);
                p[mt][h] += __shfl_xor_sync(0xffffffffu, p[mt][h], 2);
            }
        }
        __syncthreads();
        float* red = (float*)smem;                      // [128][4]
        if (lr == 0) {
#pragma unroll
            for (int mt = 0; mt < 4; mt++) {
                const int rl = warp_m * 64 + mt * 16 + lq;
                red[rl * 4 + warp_n]       = p[mt][0];
                red[(rl + 8) * 4 + warp_n] = p[mt][1];
            }
        }
        __syncthreads();
        if (tid < 128) {
            float s = red[tid * 4] + red[tid * 4 + 1] + red[tid * 4 + 2] + red[tid * 4 + 3];
            g_qpart[qt][row0 + tid] = s;
        }
    }
}

// ======================= critic kernel ====================================
__global__ __launch_bounds__(256) void critic_kernel(
    const float* __restrict__ c1, const float* __restrict__ c2,
    float* __restrict__ out)
{
    const int r = blockIdx.x * 256 + threadIdx.x;
    float q1 = g_qpart[0][r] + g_qpart[1][r] + g_qpart[2][r] + g_qpart[3][r]
             + g_xb1[r] + c1[0];
    float q2 = g_qpart[4][r] + g_qpart[5][r] + g_qpart[6][r] + g_qpart[7][r]
             + g_xb2[r] + c2[0];
    float2 s = g_sig[r];
    out[(size_t)BATCH * OUTA + r] = s.x * q1 + s.y * q2;
}

// =========================================================================
extern "C" void kernel_launch(void* const* d_in, const int* in_sizes, int n_in,
                              void* d_out, int out_size)
{
    const float* x   = (const float*)d_in[0];
    const float* W1  = (const float*)d_in[1];
    const float* W2  = (const float*)d_in[2];
    const float* A1  = (const float*)d_in[3];
    const float* b1  = (const float*)d_in[4];
    const float* c1  = (const float*)d_in[5];
    const float* A2  = (const float*)d_in[6];
    const float* b2  = (const float*)d_in[7];
    const float* c2  = (const float*)d_in[8];
    const float* Wc1 = (const float*)d_in[9];
    const float* bc1 = (const float*)d_in[10];
    const float* Wc2 = (const float*)d_in[11];
    const float* bc2 = (const float*)d_in[12];
    float* out = (float*)d_out;

    cudaFuncSetAttribute(gemm_tc_kernel,
                         cudaFuncAttributeMaxDynamicSharedMemorySize, SMEM_BYTES);

    pack_b_kernel<<<(NB * KDIM + 511) / 512, 512>>>(W1, W2, Wc1, b1, b2, A1, A2);
    pack_x_kernel<<<(BATCH * KDIM / 4) / 256, 256>>>(x);
    // chooser tile first (nblk=4), then sigma, then everything else gated.
    gemm_tc_kernel<<<dim3(1, BATCH / 128), 256, SMEM_BYTES>>>(out, 0);
    sigma_kernel<<<BATCH / 8, 256>>>(bc1, Wc2, bc2);
    gemm_tc_kernel<<<dim3(12, BATCH / 128), 256, SMEM_BYTES>>>(out, 1);
    critic_kernel<<<BATCH / 256, 256>>>(c1, c2, out);
}

// round 6
// speedup vs baseline: 7.5810x; 1.0684x over previous
#include <cuda_runtime.h>
#include <cuda_fp16.h>
#include <cstdint>
#include <math.h>

#define BATCH   65536
#define KDIM    512
#define OUTA    256
#define HID     64
#define NB      1536            // packed B rows: 12 tiles of 128

// ---------------- scratch (static device globals) ------------------------
__device__ __half g_Bh[(size_t)NB * KDIM];       // main packed B (fp16)
__device__ __half g_Bc[(size_t)128 * KDIM];      // chooser B: Wc1|b1|b2|zeros
__device__ __half g_X[(size_t)BATCH * KDIM];     // x (fp16)
__device__ float  g_xb1[BATCH];
__device__ float  g_xb2[BATCH];
__device__ float2 g_sig[BATCH];                  // (s0, s1)
__device__ float  g_qpart[8][BATCH];             // q1: 0..3, q2: 4..7

// ======================= helpers ==========================================
__device__ __forceinline__ uint32_t smem_u32(const void* p) {
    uint32_t a;
    asm("{ .reg .u64 t; cvta.to.shared.u64 t, %1; cvt.u32.u64 %0, t; }" : "=r"(a) : "l"(p));
    return a;
}
#define CP_ASYNC16(dst, src) \
    asm volatile("cp.async.cg.shared.global [%0], [%1], 16;" :: "r"(dst), "l"(src))
#define CP_COMMIT() asm volatile("cp.async.commit_group;" ::: "memory")
#define CP_WAIT(n)  asm volatile("cp.async.wait_group %0;" :: "n"(n) : "memory")

__device__ __forceinline__ void ldmatrix_x4(uint32_t& r0, uint32_t& r1,
                                            uint32_t& r2, uint32_t& r3, uint32_t addr) {
    asm volatile("ldmatrix.sync.aligned.m8n8.x4.shared.b16 {%0,%1,%2,%3}, [%4];"
        : "=r"(r0), "=r"(r1), "=r"(r2), "=r"(r3) : "r"(addr));
}
__device__ __forceinline__ void mma_f16(float* c, const uint32_t* a, const uint32_t* b) {
    asm volatile(
        "mma.sync.aligned.m16n8k16.row.col.f32.f16.f16.f32 "
        "{%0,%1,%2,%3}, {%4,%5,%6,%7}, {%8,%9}, {%0,%1,%2,%3};"
        : "+f"(c[0]), "+f"(c[1]), "+f"(c[2]), "+f"(c[3])
        : "r"(a[0]), "r"(a[1]), "r"(a[2]), "r"(a[3]), "r"(b[0]), "r"(b[1]));
}

// ======================= pack kernel ======================================
// g_Bh rows: [0,512) = interleaved W1/W2 (2j=W1_j, 2j+1=W2_j)  -> tiles 0..3
//            [512,1024)=A1^T, [1024,1536)=A2^T                 -> tiles 4..11
// g_Bc rows: [0,64)=Wc1, 64=b1, 65=b2, [66,128)=0
__global__ __launch_bounds__(512) void pack_b_kernel(
    const float* __restrict__ W1, const float* __restrict__ W2,
    const float* __restrict__ Wc1,
    const float* __restrict__ b1, const float* __restrict__ b2,
    const float* __restrict__ A1, const float* __restrict__ A2)
{
    size_t idx = (size_t)blockIdx.x * blockDim.x + threadIdx.x;
    size_t total_main = (size_t)NB * KDIM;
    if (idx < total_main) {
        int row = (int)(idx >> 9);
        int k   = (int)(idx & 511);
        float v;
        if (row < 512) {
            int j = row >> 1;
            v = (row & 1) ? W2[(size_t)j * KDIM + k] : W1[(size_t)j * KDIM + k];
        }
        else if (row < 1024) v = A1[(size_t)k * KDIM + (row - 512)];
        else                 v = A2[(size_t)k * KDIM + (row - 1024)];
        g_Bh[idx] = __float2half_rn(v);
    } else {
        size_t cidx = idx - total_main;
        if (cidx >= (size_t)128 * KDIM) return;
        int row = (int)(cidx >> 9);
        int k   = (int)(cidx & 511);
        float v;
        if      (row < 64)   v = Wc1[(size_t)row * KDIM + k];
        else if (row == 64)  v = b1[k];
        else if (row == 65)  v = b2[k];
        else                 v = 0.f;
        g_Bc[cidx] = __float2half_rn(v);
    }
}

// ======================= chooser kernel ===================================
// Reads x fp32 once: emits g_X (fp16), computes x@[Wc1|b1|b2]^T via mma,
// then sigma = sigmoid(relu(h+bc1)@Wc2^T + bc2) and xb1/xb2.
// CTA: 128 rows x K=512 in 8 chunks of 64.  smem: A 16KB + B 16KB.
#define CH_SMEM 32768

__global__ __launch_bounds__(256) void chooser_kernel(
    const float* __restrict__ x,
    const float* __restrict__ bc1,
    const float* __restrict__ Wc2, const float* __restrict__ bc2)
{
    extern __shared__ char smem[];
    const uint32_t sbase = smem_u32(smem);
    const uint32_t abase = sbase;
    const uint32_t bbase = sbase + 16384;
    const int tid   = threadIdx.x;
    const int wid   = tid >> 5;
    const int lane  = tid & 31;
    const int row0  = blockIdx.x * 128;

    const int warp_m = wid & 1;
    const int warp_n = wid >> 1;
    const int lq  = lane >> 2;
    const int lr  = lane & 3;
    const int t8  = lane >> 3;
    const int r8  = lane & 7;

    float acc[4][4][4];
#pragma unroll
    for (int mt = 0; mt < 4; mt++)
#pragma unroll
        for (int nt = 0; nt < 4; nt++)
#pragma unroll
            for (int i = 0; i < 4; i++) acc[mt][nt][i] = 0.f;

    for (int ck = 0; ck < 8; ck++) {
        const int k0 = ck * 64;
        __syncthreads();                      // smem reuse vs previous mma

        // B chunk via cp.async: 128 rows x 64 halves
#pragma unroll
        for (int i = 0; i < 4; i++) {
            int lin = tid + i * 256;          // 0..1023
            int row = lin >> 3;
            int c   = lin & 7;
            const __half* src = g_Bc + (size_t)row * KDIM + k0 + c * 8;
            CP_ASYNC16(bbase + row * 128 + ((c ^ (row & 7)) << 4), src);
        }
        CP_COMMIT();

        // A chunk: fp32 load -> fp16 -> smem (swizzled) + g_X
#pragma unroll
        for (int i = 0; i < 8; i++) {
            int lin = tid + i * 256;          // 0..2047 float4s
            int row = lin >> 4;               // 0..127
            int f4  = lin & 15;               // 0..15 (64 floats/row)
            float4 v = __ldg((const float4*)(x + (size_t)(row0 + row) * KDIM + k0) + f4);
            __half2 h0 = __floats2half2_rn(v.x, v.y);
            __half2 h1 = __floats2half2_rn(v.z, v.w);
            uint2 u;
            u.x = *(uint32_t*)&h0;
            u.y = *(uint32_t*)&h1;
            ((uint2*)(g_X + (size_t)(row0 + row) * KDIM + k0))[f4] = u;
            int c   = f4 >> 1;
            int sub = f4 & 1;
            *(uint2*)(smem + row * 128 + ((c ^ (row & 7)) << 4) + sub * 8) = u;
        }
        CP_WAIT(0);
        __syncthreads();

#pragma unroll
        for (int kk = 0; kk < 4; kk++) {
            uint32_t af[4][4];
#pragma unroll
            for (int mt = 0; mt < 4; mt++) {
                int arow = warp_m * 64 + mt * 16 + ((t8 & 1) << 3) + r8;
                int ac   = kk * 2 + (t8 >> 1);
                uint32_t addr = abase + arow * 128 + ((ac ^ (arow & 7)) << 4);
                ldmatrix_x4(af[mt][0], af[mt][1], af[mt][2], af[mt][3], addr);
            }
            uint32_t bf[4][2];
#pragma unroll
            for (int nt2 = 0; nt2 < 2; nt2++) {
                int brow = warp_n * 32 + nt2 * 16 + ((t8 >> 1) << 3) + r8;
                int bc   = kk * 2 + (t8 & 1);
                uint32_t addr = bbase + brow * 128 + ((bc ^ (brow & 7)) << 4);
                ldmatrix_x4(bf[nt2 * 2][0], bf[nt2 * 2][1],
                            bf[nt2 * 2 + 1][0], bf[nt2 * 2 + 1][1], addr);
            }
#pragma unroll
            for (int mt = 0; mt < 4; mt++)
#pragma unroll
                for (int nt = 0; nt < 4; nt++)
                    mma_f16(acc[mt][nt], af[mt], bf[nt]);
        }
    }
    __syncthreads();

    // ---------------- epilogue: sigma + xb ----------------
    // cols 0..63 = h, col 64 = xb1, col 65 = xb2
    float* red = (float*)smem;                // [128][2 warps][2 logits]
    if (warp_n < 2) {
        float p0[4][2], p1[4][2];
#pragma unroll
        for (int mt = 0; mt < 4; mt++)
#pragma unroll
            for (int h = 0; h < 2; h++) { p0[mt][h] = 0.f; p1[mt][h] = 0.f; }
#pragma unroll
        for (int mt = 0; mt < 4; mt++) {
#pragma unroll
            for (int nt = 0; nt < 4; nt++) {
                const int c0 = warp_n * 32 + nt * 8 + 2 * lr;
                const float w00 = __ldg(&Wc2[c0]),      w01 = __ldg(&Wc2[c0 + 1]);
                const float w10 = __ldg(&Wc2[64 + c0]), w11 = __ldg(&Wc2[64 + c0 + 1]);
                const float bb0 = __ldg(&bc1[c0]),      bb1 = __ldg(&bc1[c0 + 1]);
                float hA0 = fmaxf(acc[mt][nt][0] + bb0, 0.f);
                float hA1 = fmaxf(acc[mt][nt][1] + bb1, 0.f);
                float hB0 = fmaxf(acc[mt][nt][2] + bb0, 0.f);
                float hB1 = fmaxf(acc[mt][nt][3] + bb1, 0.f);
                p0[mt][0] = fmaf(hA0, w00, fmaf(hA1, w01, p0[mt][0]));
                p1[mt][0] = fmaf(hA0, w10, fmaf(hA1, w11, p1[mt][0]));
                p0[mt][1] = fmaf(hB0, w00, fmaf(hB1, w01, p0[mt][1]));
                p1[mt][1] = fmaf(hB0, w10, fmaf(hB1, w11, p1[mt][1]));
            }
        }
#pragma unroll
        for (int mt = 0; mt < 4; mt++) {
#pragma unroll
            for (int h = 0; h < 2; h++) {
                p0[mt][h] += __shfl_xor_sync(0xffffffffu, p0[mt][h], 1);
                p0[mt][h] += __shfl_xor_sync(0xffffffffu, p0[mt][h], 2);
                p1[mt][h] += __shfl_xor_sync(0xffffffffu, p1[mt][h], 1);
                p1[mt][h] += __shfl_xor_sync(0xffffffffu, p1[mt][h], 2);
            }
        }
        if (lr == 0) {
#pragma unroll
            for (int mt = 0; mt < 4; mt++) {
                const int rl = warp_m * 64 + mt * 16 + lq;
                red[(rl * 2 + warp_n) * 2 + 0]       = p0[mt][0];
                red[(rl * 2 + warp_n) * 2 + 1]       = p1[mt][0];
                red[((rl + 8) * 2 + warp_n) * 2 + 0] = p0[mt][1];
                red[((rl + 8) * 2 + warp_n) * 2 + 1] = p1[mt][1];
            }
        }
    } else if (warp_n == 2 && lr == 0) {
        // cols 64, 65 -> xb1, xb2  (only nt=0 has them)
#pragma unroll
        for (int mt = 0; mt < 4; mt++) {
            const int rA = row0 + warp_m * 64 + mt * 16 + lq;
            g_xb1[rA]     = acc[mt][0][0];
            g_xb2[rA]     = acc[mt][0][1];
            g_xb1[rA + 8] = acc[mt][0][2];
            g_xb2[rA + 8] = acc[mt][0][3];
        }
    }
    __syncthreads();

    if (tid < 128) {
        float l0 = red[(tid * 2 + 0) * 2 + 0] + red[(tid * 2 + 1) * 2 + 0] + __ldg(&bc2[0]);
        float l1 = red[(tid * 2 + 0) * 2 + 1] + red[(tid * 2 + 1) * 2 + 1] + __ldg(&bc2[1]);
        float s0 = 1.f / (1.f + expf(-l0));
        float s1 = 1.f / (1.f + expf(-l1));
        g_sig[row0 + tid] = make_float2(s0, s1);
    }
}

// ======================= fp16 mma.sync GEMM ===============================
// CTA tile 128x128, warp tile 64x32, K-chunk 64, 3-stage cp.async pipeline.
#define STAGE_BYTES 32768
#define SMEM_BYTES  (3 * STAGE_BYTES)     // 98304

__global__ __launch_bounds__(256, 2) void gemm_tc_kernel(float* __restrict__ out)
{
    extern __shared__ char smem[];
    const uint32_t sbase = smem_u32(smem);
    const int tid   = threadIdx.x;
    const int wid   = tid >> 5;
    const int lane  = tid & 31;
    const int bx    = blockIdx.x;              // 0..11
    const int row0  = blockIdx.y * 128;
    const int colbase = bx * 128;

    const int warp_m = wid & 1;
    const int warp_n = wid >> 1;
    const int lq  = lane >> 2;
    const int lr  = lane & 3;
    const int t8  = lane >> 3;
    const int r8  = lane & 7;

    auto load_chunk = [&](int stage, int k0) {
        uint32_t ab = sbase + stage * STAGE_BYTES;
        uint32_t bb = ab + 16384;
#pragma unroll
        for (int i = 0; i < 4; i++) {
            int lin = tid + i * 256;
            int row = lin >> 3;
            int c   = lin & 7;
            const __half* src = g_X + (size_t)(row0 + row) * KDIM + k0 + c * 8;
            CP_ASYNC16(ab + row * 128 + ((c ^ (row & 7)) << 4), src);
        }
#pragma unroll
        for (int i = 0; i < 4; i++) {
            int lin = tid + i * 256;
            int row = lin >> 3;
            int c   = lin & 7;
            const __half* src = g_Bh + (size_t)(colbase + row) * KDIM + k0 + c * 8;
            CP_ASYNC16(bb + row * 128 + ((c ^ (row & 7)) << 4), src);
        }
    };

    float acc[4][4][4];
#pragma unroll
    for (int mt = 0; mt < 4; mt++)
#pragma unroll
        for (int nt = 0; nt < 4; nt++)
#pragma unroll
            for (int i = 0; i < 4; i++) acc[mt][nt][i] = 0.f;

    load_chunk(0, 0);  CP_COMMIT();
    load_chunk(1, 64); CP_COMMIT();

    for (int ch = 0; ch < 8; ch++) {
        const int stage = ch % 3;
        if (ch + 2 < 8) { load_chunk((ch + 2) % 3, (ch + 2) * 64); CP_COMMIT(); }
        if (ch < 6)       CP_WAIT(2);
        else if (ch == 6) CP_WAIT(1);
        else              CP_WAIT(0);
        __syncthreads();

        const uint32_t ab = sbase + stage * STAGE_BYTES;
        const uint32_t bb = ab + 16384;

#pragma unroll
        for (int kk = 0; kk < 4; kk++) {
            uint32_t af[4][4];
#pragma unroll
            for (int mt = 0; mt < 4; mt++) {
                int arow = warp_m * 64 + mt * 16 + ((t8 & 1) << 3) + r8;
                int ac   = kk * 2 + (t8 >> 1);
                uint32_t addr = ab + arow * 128 + ((ac ^ (arow & 7)) << 4);
                ldmatrix_x4(af[mt][0], af[mt][1], af[mt][2], af[mt][3], addr);
            }
            uint32_t bf[4][2];
#pragma unroll
            for (int nt2 = 0; nt2 < 2; nt2++) {
                int brow = warp_n * 32 + nt2 * 16 + ((t8 >> 1) << 3) + r8;
                int bc   = kk * 2 + (t8 & 1);
                uint32_t addr = bb + brow * 128 + ((bc ^ (brow & 7)) << 4);
                ldmatrix_x4(bf[nt2 * 2][0], bf[nt2 * 2][1],
                            bf[nt2 * 2 + 1][0], bf[nt2 * 2 + 1][1], addr);
            }
#pragma unroll
            for (int mt = 0; mt < 4; mt++)
#pragma unroll
                for (int nt = 0; nt < 4; nt++)
                    mma_f16(acc[mt][nt], af[mt], bf[nt]);
        }
        __syncthreads();
    }

    // =================== fused epilogue ===================================
    if (bx < 4) {
        // interleaved W1/W2: (c0,c1) = (y1_j, y2_j), j = c0/2.
#pragma unroll
        for (int mt = 0; mt < 4; mt++) {
            const int rA = row0 + warp_m * 64 + mt * 16 + lq;
            const float2 sA = __ldg(&g_sig[rA]);
            const float2 sB = __ldg(&g_sig[rA + 8]);
#pragma unroll
            for (int nt = 0; nt < 4; nt++) {
                const int col = bx * 64 + warp_n * 16 + nt * 4 + lr;
                out[(size_t)rA * OUTA + col] =
                    fmaf(sA.x, acc[mt][nt][0], sA.y * acc[mt][nt][1]);
                out[(size_t)(rA + 8) * OUTA + col] =
                    fmaf(sB.x, acc[mt][nt][2], sB.y * acc[mt][nt][3]);
            }
        }
    } else {
        // quadratic tiles: fused row-dot with fp16 x
        const int qt = bx - 4;                          // 0..7
        const int jbase = (qt < 4 ? qt : qt - 4) * 128;
        float p[4][2];
#pragma unroll
        for (int mt = 0; mt < 4; mt++) { p[mt][0] = 0.f; p[mt][1] = 0.f; }
#pragma unroll
        for (int mt = 0; mt < 4; mt++) {
            const int rA = row0 + warp_m * 64 + mt * 16 + lq;
#pragma unroll
            for (int nt = 0; nt < 4; nt++) {
                const int j = jbase + warp_n * 32 + nt * 8 + 2 * lr;
                const __half2 h0 = __ldg((const __half2*)(g_X + (size_t)rA * KDIM + j));
                const __half2 h1 = __ldg((const __half2*)(g_X + (size_t)(rA + 8) * KDIM + j));
                const float2 x0 = __half22float2(h0);
                const float2 x1 = __half22float2(h1);
                p[mt][0] = fmaf(acc[mt][nt][0], x0.x, fmaf(acc[mt][nt][1], x0.y, p[mt][0]));
                p[mt][1] = fmaf(acc[mt][nt][2], x1.x, fmaf(acc[mt][nt][3], x1.y, p[mt][1]));
            }
        }
#pragma unroll
        for (int mt = 0; mt < 4; mt++) {
#pragma unroll
            for (int h = 0; h < 2; h++) {
                p[mt][h] += __shfl_xor_sync(0xffffffffu, p[mt][h], 1);
                p[mt][h] += __shfl_xor_sync(0xffffffffu, p[mt][h], 2);
            }
        }
        __syncthreads();
        float* red = (float*)smem;                      // [128][4]
        if (lr == 0) {
#pragma unroll
            for (int mt = 0; mt < 4; mt++) {
                const int rl = warp_m * 64 + mt * 16 + lq;
                red[rl * 4 + warp_n]       = p[mt][0];
                red[(rl + 8) * 4 + warp_n] = p[mt][1];
            }
        }
        __syncthreads();
        if (tid < 128) {
            float s = red[tid * 4] + red[tid * 4 + 1] + red[tid * 4 + 2] + red[tid * 4 + 3];
            g_qpart[qt][row0 + tid] = s;
        }
    }
}

// ======================= critic kernel ====================================
__global__ __launch_bounds__(256) void critic_kernel(
    const float* __restrict__ c1, const float* __restrict__ c2,
    float* __restrict__ out)
{
    const int r = blockIdx.x * 256 + threadIdx.x;
    float q1 = g_qpart[0][r] + g_qpart[1][r] + g_qpart[2][r] + g_qpart[3][r]
             + g_xb1[r] + c1[0];
    float q2 = g_qpart[4][r] + g_qpart[5][r] + g_qpart[6][r] + g_qpart[7][r]
             + g_xb2[r] + c2[0];
    float2 s = g_sig[r];
    out[(size_t)BATCH * OUTA + r] = s.x * q1 + s.y * q2;
}

// =========================================================================
extern "C" void kernel_launch(void* const* d_in, const int* in_sizes, int n_in,
                              void* d_out, int out_size)
{
    const float* x   = (const float*)d_in[0];
    const float* W1  = (const float*)d_in[1];
    const float* W2  = (const float*)d_in[2];
    const float* A1  = (const float*)d_in[3];
    const float* b1  = (const float*)d_in[4];
    const float* c1  = (const float*)d_in[5];
    const float* A2  = (const float*)d_in[6];
    const float* b2  = (const float*)d_in[7];
    const float* c2  = (const float*)d_in[8];
    const float* Wc1 = (const float*)d_in[9];
    const float* bc1 = (const float*)d_in[10];
    const float* Wc2 = (const float*)d_in[11];
    const float* bc2 = (const float*)d_in[12];
    float* out = (float*)d_out;

    cudaFuncSetAttribute(gemm_tc_kernel,
                         cudaFuncAttributeMaxDynamicSharedMemorySize, SMEM_BYTES);

    pack_b_kernel<<<((NB + 128) * KDIM + 511) / 512, 512>>>(W1, W2, Wc1, b1, b2, A1, A2);
    chooser_kernel<<<BATCH / 128, 256, CH_SMEM>>>(x, bc1, Wc2, bc2);
    gemm_tc_kernel<<<dim3(12, BATCH / 128), 256, SMEM_BYTES>>>(out);
    critic_kernel<<<BATCH / 256, 256>>>(c1, c2, out);
}